// round 1
// baseline (speedup 1.0000x reference)
#include <cuda_runtime.h>
#include <math.h>

#define BATCH 8
#define CIN   64
#define HH    128
#define WW    128
#define COUT  64

// Scratch (device globals; no allocations allowed)
__device__ __align__(16) float g_xnhwc[BATCH*HH*WW*CIN];   // 33.5 MB
__device__ __align__(16) float g_field[BATCH*HH*WW*27];    // 14.2 MB: [2k]=dy_k,[2k+1]=dx_k,[18+k]=sigmoid(mask_k)
__device__ __align__(16) float g_wr[9*CIN*COUT];           // w_dcn repacked [k][c][o]

// ---------------- transpose NCHW -> NHWC ----------------
__global__ void k_transpose(const float* __restrict__ x) {
    __shared__ float tile[32][33];
    int bh = blockIdx.z;
    int b = bh >> 7, h = bh & 127;
    int w0 = blockIdx.x * 32;
    int c0 = blockIdx.y * 32;
    int tx = threadIdx.x, ty = threadIdx.y;
    const float* src = x + ((b*CIN + c0)*HH + h)*WW + w0;
#pragma unroll
    for (int j = 0; j < 4; j++)
        tile[ty + 8*j][tx] = src[(ty + 8*j)*(HH*WW) + tx];
    __syncthreads();
    float* dst = g_xnhwc + ((b*HH + h)*WW + w0)*CIN + c0;
#pragma unroll
    for (int j = 0; j < 4; j++)
        dst[(ty + 8*j)*CIN + tx] = tile[tx][ty + 8*j];
}

// ---------------- repack w_dcn (o,c,ky,kx) -> [k][c][o] ----------------
__global__ void k_repack(const float* __restrict__ wdcn) {
    int i = blockIdx.x*256 + threadIdx.x;
    if (i >= 9*CIN*COUT) return;
    int o = i % COUT;
    int c = (i / COUT) % CIN;
    int k = i / (COUT*CIN);
    g_wr[i] = wdcn[(o*CIN + c)*9 + k];
}

// ---------------- offset conv: x (NCHW) -> field (B,H,W,27) ----------------
// tile 8 rows x 16 cols, 128 threads, smem x-tile [64][10*18] channel-major
__global__ void __launch_bounds__(128) k_offconv(
        const float* __restrict__ x, const float* __restrict__ woff,
        const float* __restrict__ boff) {
    extern __shared__ float sm[];
    float* xs = sm;               // [64][180]  (10 rows * 18 cols)
    float* ws = sm + 64*180;      // [64][28]   current-k weight slice (padded)
    int b  = blockIdx.z;
    int h0 = blockIdx.y << 3;
    int w0 = blockIdx.x << 4;
    int tid = threadIdx.x;

    // fill haloed x tile (zero padding)
    for (int e = tid; e < 64*180; e += 128) {
        int c = e / 180;
        int rem = e - c*180;
        int r = rem / 18;
        int col = rem - r*18;
        int y = h0 - 1 + r, xw = w0 - 1 + col;
        float v = 0.f;
        if ((unsigned)y < HH && (unsigned)xw < WW)
            v = x[((b*CIN + c)*HH + y)*WW + xw];
        xs[e] = v;
    }

    int ty = tid >> 4, tx = tid & 15;
    float acc[27];
#pragma unroll
    for (int o = 0; o < 27; o++) acc[o] = 0.f;

#pragma unroll 1
    for (int kk = 0; kk < 9; kk++) {
        __syncthreads();   // (kk=0: xs fill done; kk>0: prev compute done before ws overwrite)
        for (int e = tid; e < 64*27; e += 128) {
            int c = e / 27;
            int o = e - c*27;
            ws[c*28 + o] = woff[(o*CIN + c)*9 + kk];
        }
        __syncthreads();
        int ky = kk/3, kx = kk - ky*3;
        int base = (ty + ky)*18 + tx + kx;
#pragma unroll 4
        for (int c = 0; c < 64; c++) {
            float xv = xs[c*180 + base];
            const float* wc = ws + c*28;
#pragma unroll
            for (int o = 0; o < 27; o++)
                acc[o] = fmaf(xv, wc[o], acc[o]);
        }
    }

    int h = h0 + ty, w = w0 + tx;
    float* f = g_field + ((b*HH + h)*WW + w)*27;
#pragma unroll
    for (int o = 0; o < 27; o++) {
        float v = acc[o] + boff[o];
        if (o >= 18) v = 1.f/(1.f + __expf(-v));   // sigmoid on mask channels
        f[o] = v;
    }
}

// ---------------- fused bilinear sample + output GEMM ----------------
// block = 64 pixels (one row segment), 256 threads
// loop k: build A[64c][64p] sampled tile, GEMM-accumulate with Bs=[c][o]
__global__ void __launch_bounds__(256) k_main(float* __restrict__ out) {
    __shared__ __align__(16) float As[64*64];
    __shared__ __align__(16) float Bs[64*64];
    __shared__ __align__(16) float fs[64*28];
    int b = blockIdx.z, h = blockIdx.y;
    int w0 = blockIdx.x << 6;
    int tid = threadIdx.x;

    {   // cache per-pixel field values
        const float* f = g_field + ((b*HH + h)*WW + w0)*27;
        for (int e = tid; e < 64*27; e += 256) {
            int p = e / 27;
            int o = e - p*27;
            fs[p*28 + o] = f[e];
        }
    }

    float acc[4][4];
#pragma unroll
    for (int i = 0; i < 4; i++)
#pragma unroll
        for (int j = 0; j < 4; j++) acc[i][j] = 0.f;

    int sp = tid >> 2, sq = tid & 3;     // sampling: pixel, channel-quarter
    int po = tid & 15, og = tid >> 4;    // gemm: pixel-quad, out-quad
    const float* xp = g_xnhwc + b*(HH*WW*CIN);

#pragma unroll 1
    for (int kk = 0; kk < 9; kk++) {
        __syncthreads();   // kk=0: fs ready; kk>0: prev GEMM done before As/Bs overwrite
        {   // load B tile for this k (identical for all blocks -> L2-resident)
            const float4* s4 = (const float4*)(g_wr + kk*(CIN*COUT));
            float4* d4 = (float4*)Bs;
#pragma unroll
            for (int e = 0; e < 4; e++) d4[tid + 256*e] = s4[tid + 256*e];
        }
        {   // bilinear sample 16 channels of pixel sp
            int ky = kk/3, kx = kk - ky*3;
            float dy = fs[sp*28 + 2*kk];
            float dx = fs[sp*28 + 2*kk + 1];
            float m  = fs[sp*28 + 18 + kk];
            float py = dy + (float)(h - 1 + ky);
            float px = dx + (float)(w0 + sp - 1 + kx);
            float fy = floorf(py), fx = floorf(px);
            int y0 = (int)fy, x0 = (int)fx;
            float ay = py - fy, ax = px - fx;
            float w00 = (1.f-ay)*(1.f-ax)*m;
            float w01 = (1.f-ay)*ax*m;
            float w10 = ay*(1.f-ax)*m;
            float w11 = ay*ax*m;
            int y1 = y0 + 1, x1 = x0 + 1;
            if (!(((unsigned)y0 < HH) && ((unsigned)x0 < WW))) w00 = 0.f;
            if (!(((unsigned)y0 < HH) && ((unsigned)x1 < WW))) w01 = 0.f;
            if (!(((unsigned)y1 < HH) && ((unsigned)x0 < WW))) w10 = 0.f;
            if (!(((unsigned)y1 < HH) && ((unsigned)x1 < WW))) w11 = 0.f;
            int yc0 = min(max(y0, 0), HH-1);
            int yc1 = min(max(y1, 0), HH-1);
            int xc0 = min(max(x0, 0), WW-1);
            int xc1 = min(max(x1, 0), WW-1);
            const float4* t00 = (const float4*)(xp + (yc0*WW + xc0)*CIN) + sq*4;
            const float4* t01 = (const float4*)(xp + (yc0*WW + xc1)*CIN) + sq*4;
            const float4* t10 = (const float4*)(xp + (yc1*WW + xc0)*CIN) + sq*4;
            const float4* t11 = (const float4*)(xp + (yc1*WW + xc1)*CIN) + sq*4;
#pragma unroll
            for (int j = 0; j < 4; j++) {
                float4 a = t00[j], bq = t01[j], cq = t10[j], dq = t11[j];
                int c = sq*16 + j*4;
                As[(c+0)*64 + sp] = w00*a.x + w01*bq.x + w10*cq.x + w11*dq.x;
                As[(c+1)*64 + sp] = w00*a.y + w01*bq.y + w10*cq.y + w11*dq.y;
                As[(c+2)*64 + sp] = w00*a.z + w01*bq.z + w10*cq.z + w11*dq.z;
                As[(c+3)*64 + sp] = w00*a.w + w01*bq.w + w10*cq.w + w11*dq.w;
            }
        }
        __syncthreads();
        {   // 64x64x64 register-tiled GEMM accumulate
            const float4* Ap = (const float4*)As;
            const float4* Bp = (const float4*)Bs;
#pragma unroll 8
            for (int c = 0; c < 64; c++) {
                float4 a  = Ap[c*16 + po];
                float4 bv = Bp[c*16 + og];
                acc[0][0] = fmaf(bv.x, a.x, acc[0][0]);
                acc[0][1] = fmaf(bv.x, a.y, acc[0][1]);
                acc[0][2] = fmaf(bv.x, a.z, acc[0][2]);
                acc[0][3] = fmaf(bv.x, a.w, acc[0][3]);
                acc[1][0] = fmaf(bv.y, a.x, acc[1][0]);
                acc[1][1] = fmaf(bv.y, a.y, acc[1][1]);
                acc[1][2] = fmaf(bv.y, a.z, acc[1][2]);
                acc[1][3] = fmaf(bv.y, a.w, acc[1][3]);
                acc[2][0] = fmaf(bv.z, a.x, acc[2][0]);
                acc[2][1] = fmaf(bv.z, a.y, acc[2][1]);
                acc[2][2] = fmaf(bv.z, a.z, acc[2][2]);
                acc[2][3] = fmaf(bv.z, a.w, acc[2][3]);
                acc[3][0] = fmaf(bv.w, a.x, acc[3][0]);
                acc[3][1] = fmaf(bv.w, a.y, acc[3][1]);
                acc[3][2] = fmaf(bv.w, a.z, acc[3][2]);
                acc[3][3] = fmaf(bv.w, a.w, acc[3][3]);
            }
        }
    }

    // write NCHW output, float4-coalesced along w
#pragma unroll
    for (int oo = 0; oo < 4; oo++) {
        int o = og*4 + oo;
        float4 v = make_float4(acc[oo][0], acc[oo][1], acc[oo][2], acc[oo][3]);
        *(float4*)(out + ((b*COUT + o)*HH + h)*WW + w0 + po*4) = v;
    }
}

extern "C" void kernel_launch(void* const* d_in, const int* in_sizes, int n_in,
                              void* d_out, int out_size) {
    const float* x    = (const float*)d_in[0];
    const float* woff = (const float*)d_in[1];
    const float* boff = (const float*)d_in[2];
    const float* wdcn = (const float*)d_in[3];
    float* out = (float*)d_out;

    k_transpose<<<dim3(WW/32, CIN/32, BATCH*HH), dim3(32, 8)>>>(x);
    k_repack<<<(9*CIN*COUT + 255)/256, 256>>>(wdcn);

    size_t smO = (size_t)(64*180 + 64*28) * sizeof(float);   // 53,248 B
    cudaFuncSetAttribute(k_offconv, cudaFuncAttributeMaxDynamicSharedMemorySize, (int)smO);
    k_offconv<<<dim3(WW/16, HH/8, BATCH), 128, smO>>>(x, woff, boff);

    k_main<<<dim3(WW/64, HH, BATCH), 256>>>(out);
}